// round 4
// baseline (speedup 1.0000x reference)
#include <cuda_runtime.h>
#include <cuda_bf16.h>

// Problem constants (fixed by the reference): 2048x2048 fp32 image,
// pass1 box = 17 (vertical) x 5 (horizontal), pass2 box = 5 x 17.
#define H_DIM 2048
#define W_DIM 2048

// Intermediate X1 = X + B1(y - X)/N1. 16 MB static device scratch (no allocs).
__device__ float g_X1[H_DIM * W_DIM];

// One guided-filter pass:
//   out[i,j] = Xin[i,j] + (sum over clamped window of (Y - Xin)) / Ncount
// with zero-padding semantics (sum only over in-bounds pixels) and
// Ncount = (#in-bounds rows) * (#in-bounds cols), computed analytically.
//
// Tiling: each 256-thread block (32 x 8) produces a TILE_H x TILE_W = 64 x 32
// output tile. D = Y - Xin is staged in smem with full halo, reduced
// horizontally (2*RH+1 taps) into a second smem array, then each thread does
// a vertical sliding-window sum over its column (8 outputs per thread).
template <int RV, int RH, int TILE_H, int TILE_W>
__global__ __launch_bounds__(256)
void guided_pass(const float* __restrict__ Xin,
                 const float* __restrict__ Y,
                 float* __restrict__ out)
{
    constexpr int HH = TILE_H + 2 * RV;   // halo rows
    constexpr int WH = TILE_W + 2 * RH;   // halo cols
    constexpr int NTHREADS = 256;
    constexpr int ROWS = TILE_H / 8;      // outputs per thread (blockDim.y = 8)

    __shared__ float sD[HH][WH];          // D = Y - Xin, with halo
    __shared__ float sHS[HH][TILE_W];     // horizontal (2*RH+1)-sum of D

    const int bx = blockIdx.x * TILE_W;
    const int by = blockIdx.y * TILE_H;
    const int tid = threadIdx.y * 32 + threadIdx.x;

    // ---- Stage D halo into shared memory (zero outside the image) ----
    #pragma unroll
    for (int idx = tid; idx < HH * WH; idx += NTHREADS) {
        const int r = idx / WH;
        const int c = idx - r * WH;
        const int gi = by + r - RV;
        const int gj = bx + c - RH;
        float d = 0.0f;
        if (gi >= 0 && gi < H_DIM && gj >= 0 && gj < W_DIM) {
            const int g = gi * W_DIM + gj;
            d = Y[g] - Xin[g];
        }
        sD[r][c] = d;
    }
    __syncthreads();

    // ---- Horizontal (2*RH+1)-tap sums ----
    #pragma unroll
    for (int idx = tid; idx < HH * TILE_W; idx += NTHREADS) {
        const int r = idx / TILE_W;
        const int c = idx - r * TILE_W;
        float s = 0.0f;
        #pragma unroll
        for (int k = 0; k < 2 * RH + 1; k++) s += sD[r][c + k];
        sHS[r][c] = s;
    }
    __syncthreads();

    // ---- Vertical sliding-window sum + epilogue ----
    const int tx = threadIdx.x;            // output column within tile
    const int r0 = threadIdx.y * ROWS;     // first output row for this thread

    float vs = 0.0f;
    #pragma unroll
    for (int k = 0; k < 2 * RV + 1; k++) vs += sHS[r0 + k][tx];

    const int gj = bx + tx;
    const int nw = min(gj + RH, W_DIM - 1) - max(gj - RH, 0) + 1;

    #pragma unroll
    for (int rr = 0; rr < ROWS; rr++) {
        const int gi = by + r0 + rr;
        const int nh = min(gi + RV, H_DIM - 1) - max(gi - RV, 0) + 1;
        const float invN = __frcp_rn((float)(nh * nw));
        const int g = gi * W_DIM + gj;
        out[g] = Xin[g] + vs * invN;
        if (rr + 1 < ROWS) {
            vs += sHS[r0 + rr + 1 + 2 * RV][tx] - sHS[r0 + rr][tx];
        }
    }
}

extern "C" void kernel_launch(void* const* d_in, const int* in_sizes, int n_in,
                              void* d_out, int out_size)
{
    const float* X = (const float*)d_in[0];
    const float* Y = (const float*)d_in[1];
    // d_in[2] is the (2,1,17,17) kernel tensor; its structure is fixed by the
    // problem definition (17x5 and 5x17 boxes), so it is hard-coded here.
    float* out = (float*)d_out;

    float* X1;
    cudaGetSymbolAddress((void**)&X1, g_X1);

    constexpr int TILE_H = 64;
    constexpr int TILE_W = 32;
    dim3 block(32, 8);
    dim3 grid(W_DIM / TILE_W, H_DIM / TILE_H);

    // Pass 1: vertical radius 8, horizontal radius 2  ->  X1
    guided_pass<8, 2, TILE_H, TILE_W><<<grid, block>>>(X, Y, X1);
    // Pass 2: vertical radius 2, horizontal radius 8  ->  final output
    guided_pass<2, 8, TILE_H, TILE_W><<<grid, block>>>(X1, Y, out);
}

// round 6
// speedup vs baseline: 1.0299x; 1.0299x over previous
#include <cuda_runtime.h>
#include <cuda_bf16.h>

// Fixed by the reference: 2048x2048 fp32, pass1 box = 17(v) x 5(h),
// pass2 box = 5(v) x 17(h); out = Xin + boxsum(y - Xin)/Ncount, zero-padded.
#define H_DIM 2048
#define W_DIM 2048

// 16 MB static scratch for the intermediate X1 (no allocations allowed).
__device__ float g_X1[H_DIM * W_DIM];

template <int RV, int RH>
__global__ __launch_bounds__(256)
void guided_pass(const float* __restrict__ Xin,
                 const float* __restrict__ Y,
                 float* __restrict__ out)
{
    constexpr int TILE_H = 32, TILE_W = 64;
    constexpr int CL  = (RH + 3) & ~3;       // float4-aligned horizontal halo (4 / 8)
    constexpr int WH  = TILE_W + 2 * CL;     // staged width: 72 / 80 (div by 4)
    constexpr int HH  = TILE_H + 2 * RV;     // staged rows: 48 / 36
    constexpr int W4  = WH / 4;
    constexpr int NTAPV = 2 * RV + 1;
    constexpr int NTAPH = 2 * RH + 1;
    constexpr float INV_N = 1.0f / (float)(NTAPV * NTAPH);
    constexpr int O = CL - RH;               // sVS col offset of output col 0's window

    __shared__ __align__(16) float sD [HH][WH];      // D = Y - Xin (halo, zero-padded)
    __shared__ __align__(16) float sVS[TILE_H][WH];  // vertical (2RV+1)-sums of D

    const int bx  = blockIdx.x * TILE_W;
    const int by  = blockIdx.y * TILE_H;
    const int tid = threadIdx.x;

    const bool interior = (by >= RV) && (by + TILE_H + RV <= H_DIM)
                       && (bx >= CL) && (bx + TILE_W + CL <= W_DIM);

    if (interior) {
        // ---- Stage D with float4 global loads (all in-bounds, aligned) ----
        const float* ybase = Y   + (by - RV) * W_DIM + (bx - CL);
        const float* xbase = Xin + (by - RV) * W_DIM + (bx - CL);
        for (int idx = tid; idx < HH * W4; idx += 256) {
            const int r = idx / W4;
            const int c = idx - r * W4;
            const float4 yv = *(const float4*)(ybase + r * W_DIM + 4 * c);
            const float4 xv = *(const float4*)(xbase + r * W_DIM + 4 * c);
            *(float4*)&sD[r][4 * c] =
                make_float4(yv.x - xv.x, yv.y - xv.y, yv.z - xv.z, yv.w - xv.w);
        }
        __syncthreads();

        // ---- Vertical sliding-window sums, float4, 8 segments x 4 rows ----
        for (int w = tid; w < W4 * 8; w += 256) {
            const int c4 = w % W4;
            const int r0 = (w / W4) * 4;
            float4 vs = make_float4(0.f, 0.f, 0.f, 0.f);
            #pragma unroll
            for (int k = 0; k < NTAPV; k++) {
                const float4 d = *(const float4*)&sD[r0 + k][4 * c4];
                vs.x += d.x; vs.y += d.y; vs.z += d.z; vs.w += d.w;
            }
            *(float4*)&sVS[r0][4 * c4] = vs;
            #pragma unroll
            for (int rr = 1; rr < 4; rr++) {
                const float4 a = *(const float4*)&sD[r0 + rr + NTAPV - 1][4 * c4];
                const float4 b = *(const float4*)&sD[r0 + rr - 1][4 * c4];
                vs.x += a.x - b.x; vs.y += a.y - b.y;
                vs.z += a.z - b.z; vs.w += a.w - b.w;
                *(float4*)&sVS[r0 + rr][4 * c4] = vs;
            }
        }
        __syncthreads();

        // ---- Horizontal sliding window in registers + epilogue ----
        const int row = tid >> 3;             // output row within tile
        const int c0  = (tid & 7) * 8;        // first of 8 output cols
        constexpr int LW = 8 + 2 * CL;        // aligned register window (16 / 24)
        float v[LW];
        #pragma unroll
        for (int q = 0; q < LW / 4; q++) {
            const float4 t = *(const float4*)&sVS[row][c0 + 4 * q];
            v[4*q] = t.x; v[4*q+1] = t.y; v[4*q+2] = t.z; v[4*q+3] = t.w;
        }
        float hs = 0.f;
        #pragma unroll
        for (int k = 0; k < NTAPH; k++) hs += v[O + k];

        const float* xrow = Xin + (by + row) * W_DIM + bx + c0;
        const float4 x0 = *(const float4*)(xrow);
        const float4 x1 = *(const float4*)(xrow + 4);
        const float xs[8] = {x0.x, x0.y, x0.z, x0.w, x1.x, x1.y, x1.z, x1.w};
        float o[8];
        #pragma unroll
        for (int i = 0; i < 8; i++) {
            o[i] = xs[i] + hs * INV_N;
            if (i < 7) hs += v[O + NTAPH + i] - v[O + i];
        }
        float* orow = out + (by + row) * W_DIM + bx + c0;
        *(float4*)(orow)     = make_float4(o[0], o[1], o[2], o[3]);
        *(float4*)(orow + 4) = make_float4(o[4], o[5], o[6], o[7]);
    } else {
        // ================= Boundary path (scalar, predicated) =================
        for (int idx = tid; idx < HH * WH; idx += 256) {
            const int r  = idx / WH;
            const int c  = idx - r * WH;
            const int gi = by + r - RV;
            const int gj = bx + c - CL;
            float d = 0.f;
            if (gi >= 0 && gi < H_DIM && gj >= 0 && gj < W_DIM) {
                const int g = gi * W_DIM + gj;
                d = Y[g] - Xin[g];
            }
            sD[r][c] = d;
        }
        __syncthreads();

        for (int w = tid; w < WH * 8; w += 256) {
            const int c  = w % WH;
            const int r0 = (w / WH) * 4;
            float vs = 0.f;
            #pragma unroll
            for (int k = 0; k < NTAPV; k++) vs += sD[r0 + k][c];
            sVS[r0][c] = vs;
            #pragma unroll
            for (int rr = 1; rr < 4; rr++) {
                vs += sD[r0 + rr + NTAPV - 1][c] - sD[r0 + rr - 1][c];
                sVS[r0 + rr][c] = vs;
            }
        }
        __syncthreads();

        const int row = tid >> 3;
        const int c0  = (tid & 7) * 8;
        const int gi  = by + row;
        const int nh  = min(gi + RV, H_DIM - 1) - max(gi - RV, 0) + 1;

        float hs = 0.f;
        #pragma unroll
        for (int k = 0; k < NTAPH; k++) hs += sVS[row][c0 + O + k];

        #pragma unroll
        for (int i = 0; i < 8; i++) {
            const int gj = bx + c0 + i;
            const int nw = min(gj + RH, W_DIM - 1) - max(gj - RH, 0) + 1;
            const float invN = __frcp_rn((float)(nh * nw));
            const int g = gi * W_DIM + gj;
            out[g] = Xin[g] + hs * invN;
            if (i < 7) hs += sVS[row][c0 + O + NTAPH + i] - sVS[row][c0 + O + i];
        }
    }
}

extern "C" void kernel_launch(void* const* d_in, const int* in_sizes, int n_in,
                              void* d_out, int out_size)
{
    const float* X = (const float*)d_in[0];
    const float* Y = (const float*)d_in[1];
    // d_in[2] is the (2,1,17,17) kernel tensor; fixed 17x5 / 5x17 boxes hard-coded.
    float* out = (float*)d_out;

    float* X1;
    cudaGetSymbolAddress((void**)&X1, g_X1);

    dim3 block(256);
    dim3 grid(W_DIM / 64, H_DIM / 32);

    // Pass 1: vertical radius 8, horizontal radius 2  ->  X1 (scratch)
    guided_pass<8, 2><<<grid, block>>>(X, Y, X1);
    // Pass 2: vertical radius 2, horizontal radius 8  ->  final output
    guided_pass<2, 8><<<grid, block>>>(X1, Y, out);
}